// round 6
// baseline (speedup 1.0000x reference)
#include <cuda_runtime.h>
#include <math_constants.h>

#define BB 8
#define NN 4096
#define NS 1024
#define THREADS 1024
#define TOPK 4

// Per-batch loss scratch (no device allocation allowed).
__device__ float g_batchLoss[BB];

// rowKey: [63:32] d2 bits  [31:16] row id  [15:0] col id  (lexmin == reference order)
// rowTop entries: [41:10] d2 bits  [9:0] col id, ascending; ~0ULL = invalid.
#define MKKEY(vb, rid, cs) ((((unsigned long long)(vb)) << 32) | \
                            ((unsigned)(rid) << 16) | (unsigned)(cs))

struct SmemLayout {
    float4 p1s[NS];                      // 16 KB  S1 points by row id
    float4 p2sC[NS];                     // 16 KB  S2 points, COMPACT; .w = col id
    unsigned long long rowKey[NS];       //  8 KB  best key, by row id (~0 = dead row)
    unsigned long long rowTop[NS*TOPK];  // 32 KB  top-4 packed (d2<<10|col), sorted
    unsigned short colPos[NS];           //  2 KB  col id -> compact pos
    unsigned char  colAlive[NS];         //  1 KB
};
#define SMEM_BYTES ((int)sizeof(SmemLayout))

__global__ __launch_bounds__(THREADS, 1)
void emd_batch_kernel(const float* __restrict__ S1,
                      const float* __restrict__ S2,
                      const int*   __restrict__ idxs) {
    extern __shared__ char smem_raw[];
    SmemLayout* sm = reinterpret_cast<SmemLayout*>(smem_raw);
    float4* p1s  = sm->p1s;
    float4* p2sC = sm->p2sC;
    unsigned long long* rowKey = sm->rowKey;
    unsigned long long* rowTop = sm->rowTop;
    unsigned short* colPos = sm->colPos;
    unsigned char*  colAlive = sm->colAlive;

    const int b = blockIdx.x;
    const int t = threadIdx.x;

    // ---- gather sampled points into shared ----
    {
        int id = idxs[b * NS + t];
        const float* q1 = S1 + ((long)b * NN + id) * 3;
        const float* q2 = S2 + ((long)b * NN + id) * 3;
        p1s[t]  = make_float4(q1[0], q1[1], q1[2], 0.f);
        p2sC[t] = make_float4(q2[0], q2[1], q2[2], __int_as_float(t));
        colPos[t] = (unsigned short)t;
        colAlive[t] = 1;
    }
    __syncthreads();

    // ---- init top-4 per row: thread t owns row t ----
    {
        float4 p = p1s[t];
        unsigned long long k0 = ~0ULL, k1 = ~0ULL, k2 = ~0ULL, k3 = ~0ULL;
        #pragma unroll 4
        for (int c = 0; c < NS; ++c) {               // uniform c -> LDS broadcast
            float4 q = p2sC[c];
            float dx = p.x - q.x, dy = p.y - q.y, dz = p.z - q.z;
            float d2 = fmaf(dz, dz, fmaf(dy, dy, dx * dx));
            unsigned long long k =
                (((unsigned long long)__float_as_uint(d2)) << 10) | (unsigned)c;
            if (k < k3) {
                if (k < k2) { k3 = k2;
                    if (k < k1) { k2 = k1;
                        if (k < k0) { k1 = k0; k0 = k; } else k1 = k;
                    } else k2 = k;
                } else k3 = k;
            }
        }
        rowTop[t*TOPK+0] = k0; rowTop[t*TOPK+1] = k1;
        rowTop[t*TOPK+2] = k2; rowTop[t*TOPK+3] = k3;
        rowKey[t] = MKKEY((unsigned)(k0 >> 10), t, (unsigned)(k0 & 0x3FFu));
    }
    __syncthreads();

    if (t >= 32) return;   // single warp runs the sequential greedy chain

    const unsigned FULL = 0xffffffffu;
    const int lane = t;
    float loss = 0.f;

    // ---- register-resident segment minima: lane owns rows [lane*32, lane*32+32) ----
    unsigned long long mySeg;
    {
        unsigned long long m = ~0ULL;
        #pragma unroll 8
        for (int i = 0; i < 32; ++i) {
            unsigned long long k = rowKey[lane * 32 + i];
            if (k < m) m = k;
        }
        mySeg = m;
    }
    __syncwarp(FULL);

    for (int it = 0; it < NS; ++it) {
        const int nAlive = NS - it;               // alive cols (compact count)
        int rid, csel;
        float v;

        for (;;) {
            // ---- O(1) global lexmin over 32 register segment minima ----
            unsigned hi  = (unsigned)(mySeg >> 32);
            unsigned lo  = (unsigned)mySeg;
            unsigned mhi = __reduce_min_sync(FULL, hi);
            unsigned mlo = __reduce_min_sync(FULL, (hi == mhi) ? lo : 0xFFFFFFFFu);
            v    = __uint_as_float(mhi);
            rid  = (int)(mlo >> 16);
            csel = (int)(mlo & 0xFFFFu);

            if (colAlive[csel]) break;            // cached entry valid -> true min

            const int seg = rid >> 5;

            // ---- scan the row's top-4 cache: first entry with alive col wins ----
            unsigned long long e = (lane < TOPK) ? rowTop[rid*TOPK + lane] : ~0ULL;
            bool ok = (lane < TOPK) && (e != ~0ULL) && colAlive[e & 0x3FFu];
            unsigned bal = __ballot_sync(FULL, ok);

            if (bal) {
                unsigned long long ek = __shfl_sync(FULL, e, __ffs(bal) - 1);
                if (lane == 0)
                    rowKey[rid] = MKKEY((unsigned)(ek >> 10), rid,
                                        (unsigned)(ek & 0x3FFu));
            } else {
                // ---- all cached cols dead: full rescan, refill top-4 ----
                float4 p = p1s[rid];
                unsigned long long k0 = ~0ULL, k1 = ~0ULL, k2 = ~0ULL, k3 = ~0ULL;
                #pragma unroll 4
                for (int j = lane; j < nAlive; j += 32) {
                    float4 q = p2sC[j];
                    float dx = p.x - q.x, dy = p.y - q.y, dz = p.z - q.z;
                    float d2 = fmaf(dz, dz, fmaf(dy, dy, dx * dx));
                    unsigned long long k =
                        (((unsigned long long)__float_as_uint(d2)) << 10) |
                        (unsigned)__float_as_int(q.w);
                    if (k < k3) {
                        if (k < k2) { k3 = k2;
                            if (k < k1) { k2 = k1;
                                if (k < k0) { k1 = k0; k0 = k; } else k1 = k;
                            } else k2 = k;
                        } else k3 = k;
                    }
                }
                // ---- butterfly merge of sorted quads: keep global lowest 4 ----
                #pragma unroll
                for (int off = 16; off > 0; off >>= 1) {
                    unsigned long long b0 = __shfl_xor_sync(FULL, k0, off);
                    unsigned long long b1 = __shfl_xor_sync(FULL, k1, off);
                    unsigned long long b2 = __shfl_xor_sync(FULL, k2, off);
                    unsigned long long b3 = __shfl_xor_sync(FULL, k3, off);
                    // half-cleaner: t_i = min(a_i, b_{3-i}) -> bitonic lowest-4
                    unsigned long long t0 = (k0 < b3) ? k0 : b3;
                    unsigned long long t1 = (k1 < b2) ? k1 : b2;
                    unsigned long long t2 = (k2 < b1) ? k2 : b1;
                    unsigned long long t3 = (k3 < b0) ? k3 : b0;
                    // bitonic sort of 4: dist 2 then dist 1
                    unsigned long long u0 = (t0 < t2) ? t0 : t2;
                    unsigned long long u2 = (t0 < t2) ? t2 : t0;
                    unsigned long long u1 = (t1 < t3) ? t1 : t3;
                    unsigned long long u3 = (t1 < t3) ? t3 : t1;
                    k0 = (u0 < u1) ? u0 : u1;
                    k1 = (u0 < u1) ? u1 : u0;
                    k2 = (u2 < u3) ? u2 : u3;
                    k3 = (u2 < u3) ? u3 : u2;
                }
                if (lane < TOPK) {
                    unsigned long long w = (lane == 0) ? k0 : (lane == 1) ? k1
                                         : (lane == 2) ? k2 : k3;
                    rowTop[rid*TOPK + lane] = w;
                }
                if (lane == 0)
                    rowKey[rid] = MKKEY((unsigned)(k0 >> 10), rid,
                                        (unsigned)(k0 & 0x3FFu));
            }
            __syncwarp(FULL);

            // ---- recompute this segment's min (32 consecutive LDS.64 + REDUX) ----
            unsigned long long kk = rowKey[seg * 32 + lane];
            unsigned h2 = (unsigned)(kk >> 32), l2 = (unsigned)kk;
            unsigned m2 = __reduce_min_sync(FULL, h2);
            unsigned n2 = __reduce_min_sync(FULL, (h2 == m2) ? l2 : 0xFFFFFFFFu);
            if (lane == seg) mySeg = (((unsigned long long)m2) << 32) | n2;
            __syncwarp(FULL);
        }

        // ---- accept (rid, csel, v): kill row (sentinel) + swap-remove col ----
        {
            const int seg = rid >> 5;
            const int lastP = nAlive - 1;
            float4 fLast = p2sC[lastP];           // independent broadcast loads
            int cpos = colPos[csel];
            if (lane == 0) {
                loss += sqrtf(v);                 // reference accumulation order
                rowKey[rid] = ~0ULL;
                p2sC[cpos] = fLast;               // col id rides in .w
                colPos[(unsigned)__float_as_int(fLast.w)] = (unsigned short)cpos;
                colAlive[csel] = 0;
            }
            __syncwarp(FULL);
            unsigned long long kk = rowKey[seg * 32 + lane];
            unsigned h2 = (unsigned)(kk >> 32), l2 = (unsigned)kk;
            unsigned m2 = __reduce_min_sync(FULL, h2);
            unsigned n2 = __reduce_min_sync(FULL, (h2 == m2) ? l2 : 0xFFFFFFFFu);
            if (lane == seg) mySeg = (((unsigned long long)m2) << 32) | n2;
            __syncwarp(FULL);
        }
    }

    if (lane == 0) g_batchLoss[b] = loss / (float)NS;
}

__global__ void emd_final_kernel(float* __restrict__ out) {
    float s = 0.f;
    #pragma unroll
    for (int b = 0; b < BB; ++b) s += g_batchLoss[b];
    out[0] = s / (float)BB;
}

extern "C" void kernel_launch(void* const* d_in, const int* in_sizes, int n_in,
                              void* d_out, int out_size) {
    const float* S1  = (const float*)d_in[0];
    const float* S2  = (const float*)d_in[1];
    const int*   idx = (const int*)  d_in[2];
    float* out = (float*)d_out;

    // Opt in to >48KB dynamic shared memory (non-stream API: immediate,
    // alloc-free, idempotent — safe under graph capture).
    cudaFuncSetAttribute(emd_batch_kernel,
                         cudaFuncAttributeMaxDynamicSharedMemorySize, SMEM_BYTES);

    emd_batch_kernel<<<BB, THREADS, SMEM_BYTES>>>(S1, S2, idx);
    emd_final_kernel<<<1, 1>>>(out);
}